// round 16
// baseline (speedup 1.0000x reference)
#include <cuda_runtime.h>

#define SQ   1024
#define BS   64
#define HD   512
#define ED   256
#define VB   32000
#define G3   1536
#define EOSV 2
#define NEOS 32

#define NBG   8            // batch groups (8 rows each)
#define NPAIR 4            // CTA handles bgs {pair, 4+pair} in warp halves
#define NRG   32           // j groups (16 h-dims each)
#define NCTA  (NPAIR*NRG)  // 128 CTAs, 1/SM, uniform dual-recurrence

#define STAGGER_CYC 3000ull   // anti-phase seed for half B

#define PSTR 14            // psum row stride (floats), 12 used
#define SM_H      (8*HD)                     // per half: 16KB h
#define SM_PSUM   (8*16*PSTR)                // per half: 7KB psum
#define SM_HALF   (SM_H + SM_PSUM)
#define GRU_SMEM  (2 * SM_HALF * 4)          // 47104 B

typedef unsigned long long u64;

// ------------------- device scratch (static only; no allocs) ----------------
__device__ float    g_Gtab[(size_t)VB * G3];   // ~197MB input-projection table
__device__ float    g_h[2][BS * HD];           // double-buffered hidden state
__device__ int      g_dest[SQ * BS];           // EOS compaction slot or -1
__device__ unsigned g_ctr[NBG * 64];           // per-bg counters, 256B stride

// ------------------- packed f32x2 helpers ----------------------------------
__device__ __forceinline__ u64 ffma2(u64 a, u64 b, u64 c) {
    u64 d;
    asm("fma.rn.f32x2 %0, %1, %2, %3;" : "=l"(d) : "l"(a), "l"(b), "l"(c));
    return d;
}
__device__ __forceinline__ float2 unpack2(u64 v) {
    float2 f;
    asm("mov.b64 {%0, %1}, %2;" : "=f"(f.x), "=f"(f.y) : "l"(v));
    return f;
}
__device__ __forceinline__ float hsum2(u64 v) {
    float2 f = unpack2(v);
    return f.x + f.y;
}
__device__ __forceinline__ u64 bcast2(float x) {
    u64 d;
    asm("mov.b64 %0, {%1, %1};" : "=l"(d) : "f"(x));
    return d;
}
__device__ __forceinline__ unsigned ld_acq(const unsigned* p) {
    unsigned v;
    asm volatile("ld.acquire.gpu.global.u32 %0, [%1];" : "=r"(v) : "l"(p));
    return v;
}
__device__ __forceinline__ void red_release_add(unsigned* p, unsigned v) {
    asm volatile("red.release.gpu.global.add.u32 [%0], %1;" :: "l"(p), "r"(v) : "memory");
}
__device__ __forceinline__ void half_bar(int id) {
    asm volatile("bar.sync %0, 128;" :: "r"(id) : "memory");
}

// ------------------- Gtab GEMM (+fused prep): G = w_ih * emb^T + b_ih ------
__global__ void __launch_bounds__(256) gtab_kernel(
    const float* __restrict__ emb,
    const float* __restrict__ w_ih,
    const float* __restrict__ b_ih,
    const int*   __restrict__ tokens)
{
    // ---- fused prep: h0, counters, EOS scan (first 64 flat CTAs, warp 0) ----
    int fid = blockIdx.y * 12 + blockIdx.x;
    if (fid < BS && threadIdx.x < 32) {
        int b = fid, t = threadIdx.x;
        if (fid == 0 && t < NBG) g_ctr[t * 64] = 0u;
        for (int i = t; i < HD; i += 32) g_h[0][b * HD + i] = 0.f;
        int s0 = t * 32;
        int cnt = 0;
        #pragma unroll
        for (int i = 0; i < 32; i++) cnt += (tokens[b * SQ + s0 + i] == EOSV);
        int pre = cnt;
        #pragma unroll
        for (int m = 1; m < 32; m <<= 1) {
            int v = __shfl_up_sync(0xffffffffu, pre, m);
            if (t >= m) pre += v;
        }
        pre -= cnt;
        int k = pre;
        #pragma unroll
        for (int i = 0; i < 32; i++) {
            int s = s0 + i;
            bool e = (tokens[b * SQ + s] == EOSV);
            g_dest[s * BS + b] = (e && k < NEOS) ? k : -1;
            k += e;
        }
    }

    // ---- GEMM: 128x128 tile, 16-k steps, 8x8 microtile, f32x2 ----
    __shared__ float A_sT[16 * 132];
    __shared__ float B_sT[16 * 132];

    int tid = threadIdx.x;
    int tx = tid & 15, ty = tid >> 4;
    int g0 = blockIdx.x * 128;
    int t0 = blockIdx.y * 128;

    u64 acc[8][4];
    #pragma unroll
    for (int i = 0; i < 8; i++)
        #pragma unroll
        for (int j = 0; j < 4; j++) acc[i][j] = 0ull;

    for (int k0 = 0; k0 < ED; k0 += 16) {
        __syncthreads();
        #pragma unroll
        for (int i = 0; i < 2; i++) {
            int ff  = tid + i * 256;
            int row = ff >> 2;
            int c4  = (ff & 3) * 4;
            float4 va = *(const float4*)&emb[(size_t)(t0 + row) * ED + k0 + c4];
            A_sT[(c4 + 0) * 132 + row] = va.x;
            A_sT[(c4 + 1) * 132 + row] = va.y;
            A_sT[(c4 + 2) * 132 + row] = va.z;
            A_sT[(c4 + 3) * 132 + row] = va.w;
            float4 vb = *(const float4*)&w_ih[(size_t)(g0 + row) * ED + k0 + c4];
            B_sT[(c4 + 0) * 132 + row] = vb.x;
            B_sT[(c4 + 1) * 132 + row] = vb.y;
            B_sT[(c4 + 2) * 132 + row] = vb.z;
            B_sT[(c4 + 3) * 132 + row] = vb.w;
        }
        __syncthreads();
        #pragma unroll
        for (int k = 0; k < 16; k++) {
            float4 a0 = *(const float4*)&A_sT[k * 132 + ty * 4];
            float4 a1 = *(const float4*)&A_sT[k * 132 + 64 + ty * 4];
            u64 b0x = *(const u64*)&B_sT[k * 132 + tx * 4];
            u64 b0y = *(const u64*)&B_sT[k * 132 + tx * 4 + 2];
            u64 b1x = *(const u64*)&B_sT[k * 132 + 64 + tx * 4];
            u64 b1y = *(const u64*)&B_sT[k * 132 + 64 + tx * 4 + 2];
            float af[8] = {a0.x, a0.y, a0.z, a0.w, a1.x, a1.y, a1.z, a1.w};
            #pragma unroll
            for (int i = 0; i < 8; i++) {
                u64 ap = bcast2(af[i]);
                acc[i][0] = ffma2(ap, b0x, acc[i][0]);
                acc[i][1] = ffma2(ap, b0y, acc[i][1]);
                acc[i][2] = ffma2(ap, b1x, acc[i][2]);
                acc[i][3] = ffma2(ap, b1y, acc[i][3]);
            }
        }
    }

    float4 bia0 = *(const float4*)&b_ih[g0 + tx * 4];
    float4 bia1 = *(const float4*)&b_ih[g0 + 64 + tx * 4];
    #pragma unroll
    for (int i = 0; i < 8; i++) {
        int trow = t0 + (i >> 2) * 64 + ty * 4 + (i & 3);
        float2 c0 = unpack2(acc[i][0]);
        float2 c1 = unpack2(acc[i][1]);
        float2 c2 = unpack2(acc[i][2]);
        float2 c3 = unpack2(acc[i][3]);
        float4 o0 = make_float4(c0.x + bia0.x, c0.y + bia0.y, c1.x + bia0.z, c1.y + bia0.w);
        float4 o1 = make_float4(c2.x + bia1.x, c2.y + bia1.y, c3.x + bia1.z, c3.y + bia1.w);
        *(float4*)&g_Gtab[(size_t)trow * G3 + g0 + tx * 4]      = o0;
        *(float4*)&g_Gtab[(size_t)trow * G3 + g0 + 64 + tx * 4] = o1;
    }
}

// ------------------- persistent GRU recurrence ------------------------------
// 128 CTAs (4 pairs x 32 rg), 256 threads, 1/SM.  WARP-SPECIALIZED DUAL
// RECURRENCE: warps 0-3 run bg=pair, warps 4-7 run bg=4+pair — two fully
// independent instruction streams (own named barrier, own counter, own poll),
// paired 1:1 per SMSP. A half's barrier stall is filled by the other half's
// FFMA on the same schedulers; placement-independent, uniform across all SMs
// (kills the fast/slow-SM arrival spread of the 256-CTA layout).
// Within a half (128 thr): ks = lt>>4 (64-elem K slice), jl = lt&15 broadcast,
// W_hh slice in 96 u64 regs (j-indexed: identical layout for both halves).
__global__ void __launch_bounds__(256, 1) gru_kernel(
    const int*   __restrict__ tokens,
    const float* __restrict__ w_hh,
    const float* __restrict__ b_hh,
    float*       __restrict__ out)
{
    extern __shared__ float sm[];

    int tid = threadIdx.x;
    int bid = blockIdx.x;
    int pair = bid >> 5, rg = bid & 31;
    int half = tid >> 7;                 // 0 = warps 0-3, 1 = warps 4-7
    int lt   = tid & 127;
    int bg   = half * NPAIR + pair;

    float (*h_s)[HD] = (float(*)[HD])(sm + half * SM_HALF);
    float* psum = sm + half * SM_HALF + SM_H;

    int ks = lt >> 4;          // 0..7   (64-elem k slice)
    int jl = lt & 15;          // broadcast lanes
    int jG = rg * 16 + jl;

    // one-time W_hh register slice: 3 gates x 64 elems, rotated float4 order
    u64 wr[32], wz[32], wn[32];
    #pragma unroll
    for (int i4 = 0; i4 < 16; i4++) {
        int col = ks * 64 + ((i4 + 4 * ks) & 15) * 4;
        const float* r0 = &w_hh[(size_t)(0 * HD + jG) * HD + col];
        const float* r1 = &w_hh[(size_t)(1 * HD + jG) * HD + col];
        const float* r2 = &w_hh[(size_t)(2 * HD + jG) * HD + col];
        wr[2 * i4] = *(const u64*)r0;  wr[2 * i4 + 1] = *(const u64*)(r0 + 2);
        wz[2 * i4] = *(const u64*)r1;  wz[2 * i4 + 1] = *(const u64*)(r1 + 2);
        wn[2 * i4] = *(const u64*)r2;  wn[2 * i4 + 1] = *(const u64*)(r2 + 2);
    }

    // phase-2 / prefetch role: one (batch, j) per thread within the half
    int bl2 = lt >> 4;                        // 0..7
    int bG2 = bg * 8 + bl2;
    int jG2 = jG;
    float bhr = b_hh[jG2], bhz = b_hh[HD + jG2], bhn = b_hh[2 * HD + jG2];

    int tok0 = __ldg(&tokens[bG2 * SQ]);
    const float* gp0 = &g_Gtab[(size_t)tok0 * G3 + jG2];
    float pr = __ldcs(gp0), pz = __ldcs(gp0 + HD), pn = __ldcs(gp0 + 2 * HD);
    int pd = __ldg(&g_dest[bG2]);

    bool store_lane = ((ks & 1) == 0);
    int  slot = ks >> 1;                      // 0..3

    unsigned* ctr = &g_ctr[bg * 64];
    int barid = 1 + half;

    // ---- anti-phase seed: half B starts half a step late ----
    if (half == 1) {
        unsigned long long tc0 = clock64();
        while (clock64() - tc0 < STAGGER_CYC) { }
    }
    half_bar(barid);

    for (int s = 0; s < SQ; s++) {
        // ---- load h(s): 8 rows x 512 = 1024 float4 -> 8 per thread ----
        {
            const float* hsrc = &g_h[s & 1][bg * 8 * HD];
            float4 hv[8];
            #pragma unroll
            for (int i = 0; i < 8; i++) {
                int f = lt + i * 128;
                hv[i] = __ldcg((const float4*)&hsrc[(f >> 7) * HD + (f & 127) * 4]);
            }
            #pragma unroll
            for (int i = 0; i < 8; i++) {
                int f = lt + i * 128;
                *(float4*)&h_s[f >> 7][(f & 127) * 4] = hv[i];
            }
        }
        half_bar(barid);

        // ---- phase 1: split-K partials, 2 batches per pass (6 chains) ----
        #pragma unroll 2
        for (int p = 0; p < 4; p++) {
            int b0 = 2 * p, b1 = 2 * p + 1;
            u64 a0r = 0, a0z = 0, a0n = 0, a1r = 0, a1z = 0, a1n = 0;
            #pragma unroll
            for (int i4 = 0; i4 < 16; i4++) {
                int col = ks * 64 + ((i4 + 4 * ks) & 15) * 4;
                ulonglong2 h0 = *(const ulonglong2*)&h_s[b0][col];
                ulonglong2 h1 = *(const ulonglong2*)&h_s[b1][col];
                a0r = ffma2(wr[2 * i4], h0.x, a0r);
                a1r = ffma2(wr[2 * i4], h1.x, a1r);
                a0z = ffma2(wz[2 * i4], h0.x, a0z);
                a1z = ffma2(wz[2 * i4], h1.x, a1z);
                a0n = ffma2(wn[2 * i4], h0.x, a0n);
                a1n = ffma2(wn[2 * i4], h1.x, a1n);
                a0r = ffma2(wr[2 * i4 + 1], h0.y, a0r);
                a1r = ffma2(wr[2 * i4 + 1], h1.y, a1r);
                a0z = ffma2(wz[2 * i4 + 1], h0.y, a0z);
                a1z = ffma2(wz[2 * i4 + 1], h1.y, a1z);
                a0n = ffma2(wn[2 * i4 + 1], h0.y, a0n);
                a1n = ffma2(wn[2 * i4 + 1], h1.y, a1n);
            }
            float v0r = hsum2(a0r), v0z = hsum2(a0z), v0n = hsum2(a0n);
            float v1r = hsum2(a1r), v1z = hsum2(a1z), v1n = hsum2(a1n);
            // combine ks-pair (same jl, lane^16)
            v0r += __shfl_xor_sync(0xffffffffu, v0r, 16);
            v0z += __shfl_xor_sync(0xffffffffu, v0z, 16);
            v0n += __shfl_xor_sync(0xffffffffu, v0n, 16);
            v1r += __shfl_xor_sync(0xffffffffu, v1r, 16);
            v1z += __shfl_xor_sync(0xffffffffu, v1z, 16);
            v1n += __shfl_xor_sync(0xffffffffu, v1n, 16);
            if (store_lane) {
                float* p0 = &psum[(b0 * 16 + jl) * PSTR];
                float* p1 = &psum[(b1 * 16 + jl) * PSTR];
                p0[slot] = v0r;  p0[4 + slot] = v0z;  p0[8 + slot] = v0n;
                p1[slot] = v1r;  p1[4 + slot] = v1z;  p1[8 + slot] = v1n;
            }
        }

        // ---- prefetch gi(s+1)/dest(s+1): hidden under bar + next wait ----
        float nr = 0.f, nz = 0.f, nn2 = 0.f;
        int nd = -1;
        if (s + 1 < SQ) {
            int tk = __ldg(&tokens[bG2 * SQ + s + 1]);
            const float* gq = &g_Gtab[(size_t)tk * G3 + jG2];
            nr  = __ldcs(gq);
            nz  = __ldcs(gq + HD);
            nn2 = __ldcs(gq + 2 * HD);
            nd  = __ldg(&g_dest[(s + 1) * BS + bG2]);
        }
        half_bar(barid);

        // ---- phase 2: reduce 4 slots per gate, gates, store ----
        {
            const float* pp = &psum[lt * PSTR];
            float2 q0 = *(const float2*)&pp[0], q1 = *(const float2*)&pp[2];
            float2 q2 = *(const float2*)&pp[4], q3 = *(const float2*)&pp[6];
            float2 q4 = *(const float2*)&pp[8], q5 = *(const float2*)&pp[10];
            float rsum = (q0.x + q0.y) + (q1.x + q1.y);
            float zsum = (q2.x + q2.y) + (q3.x + q3.y);
            float nsum = (q4.x + q4.y) + (q5.x + q5.y);
            float hprev = h_s[bl2][jG2];

            float r  = 1.f / (1.f + __expf(-(pr + rsum + bhr)));
            float z  = 1.f / (1.f + __expf(-(pz + zsum + bhz)));
            float nx = pn + r * (nsum + bhn);
            float e2 = __expf(-2.f * nx);
            float n  = 2.f / (1.f + e2) - 1.f;          // tanh, inf-safe
            float hnew = fmaf(z, hprev - n, n);         // (1-z)*n + z*h

            g_h[(s + 1) & 1][bG2 * HD + jG2] = hnew;
            if (pd >= 0) out[((size_t)pd * BS + bG2) * HD + jG2] = hnew;
            pr = nr; pz = nz; pn = nn2; pd = nd;
        }

        // ---- per-bg barrier (32 CTAs), half-tid0 poll + half wake ----
        if (s + 1 < SQ) {
            half_bar(barid);                 // orders h stores before release
            if (lt == 0) {
                red_release_add(ctr, 1u);
                unsigned tgt = 32u * (unsigned)(s + 1);
                while (ld_acq(ctr) < tgt) { }
            }
            half_bar(barid);
        }
    }
}

// ------------------- launch -------------------------------------------------
extern "C" void kernel_launch(void* const* d_in, const int* in_sizes, int n_in,
                              void* d_out, int out_size) {
    const int*   tokens = (const int*)d_in[0];
    const float* emb    = (const float*)d_in[1];
    const float* w_ih   = (const float*)d_in[2];
    const float* w_hh   = (const float*)d_in[3];
    const float* b_ih   = (const float*)d_in[4];
    const float* b_hh   = (const float*)d_in[5];
    float* out = (float*)d_out;

    cudaFuncSetAttribute(gru_kernel,
                         cudaFuncAttributeMaxDynamicSharedMemorySize, GRU_SMEM);

    gtab_kernel<<<dim3(G3 / 128, VB / 128), 256>>>(emb, w_ih, b_ih, tokens);
    gru_kernel<<<NCTA, 256, GRU_SMEM>>>(tokens, w_hh, b_hh, out);
}